// round 11
// baseline (speedup 1.0000x reference)
#include <cuda_runtime.h>

// Problem constants (fixed shapes for SpNCN_Layer_81106162417854)
#define T_STEPS 800
#define BATCH   128
#define S_DIM   500
#define BS      (BATCH * S_DIM)          // 64000
#define M_ROWS  (T_STEPS * BATCH)        // 102400

#define DT     0.25
#define ALPHA_F ((float)(1.0 - DT / 10.0))
#define BETA_F  ((float)(1.0 - DT / 20.0))
#define KAPPA_F ((float)(1.0 - DT / 30.0))
#define THRESH_F 0.4f

// Scratch for total = input - error @ W^T  (205 MB)
__device__ float g_total[(size_t)T_STEPS * BATCH * S_DIM];

// ---------------------------------------------------------------------------
// Kernel 1: total[m,n] = inp[m,n] - sum_k err[m,k] * W[n,k]
// NUMERICS CONTRACT (validated bitwise R4-R9): per output element a serial
// ascending-k single-accumulator scalar FFMA chain; one final __fadd_rn.
// BK=20: 500 = 25*20 -> NO K-tail, 25 barriers (was 31+3). Threads <128 load
// A rows, >=128 load B rows (5 float4 each). Fragment double-buffering kept.
// ---------------------------------------------------------------------------
#define BM 128
#define BN 128
#define BK 20
#define NITER 25

__global__ __launch_bounds__(256, 2) void gemm_total_kernel(
    const float* __restrict__ inp,
    const float* __restrict__ err,
    const float* __restrict__ W)
{
    __shared__ float As[2][BK][BM];   // 20 KB
    __shared__ float Bs[2][BK][BN];   // 20 KB

    const int bm = blockIdx.y * BM;
    const int bn = blockIdx.x * BN;
    const int t  = threadIdx.x;

    // ---- load mapping: t<128 -> A row t; t>=128 -> B row t-128 ----
    const int  lrow = t & 127;
    const bool isA  = (t < 128);
    const bool lok  = isA || (bn + lrow < S_DIM);
    const float* Lp = isA ? (err + (size_t)(bm + lrow) * S_DIM)
                          : (W + (size_t)(lok ? bn + lrow : 0) * S_DIM);
    const float4 f4z = make_float4(0.f, 0.f, 0.f, 0.f);

    // ---- compute mapping: cx,ry in 0..15; fragments at +0 and +64 ----
    const int cx = t & 15;
    const int ry = t >> 4;
    const int r0 = ry * 4, r1 = ry * 4 + 64;
    const int c0 = cx * 4, c1 = cx * 4 + 64;

    float acc[8][8];
#pragma unroll
    for (int i = 0; i < 8; i++)
#pragma unroll
        for (int j = 0; j < 8; j++) acc[i][j] = 0.f;

    float4 pf[5];                           // prefetch: 5 quads of one operand
    float4 fa0[2], fa1[2], fb0[2], fb1[2];  // double-buffered fragments

    // prime tile 0
#pragma unroll
    for (int q = 0; q < 5; q++)
        pf[q] = lok ? *(const float4*)(Lp + q * 4) : f4z;
    {
        float (*dst)[BM] = isA ? As[0] : Bs[0];
#pragma unroll
        for (int q = 0; q < 5; q++) {
            dst[q * 4 + 0][lrow] = pf[q].x;  dst[q * 4 + 1][lrow] = pf[q].y;
            dst[q * 4 + 2][lrow] = pf[q].z;  dst[q * 4 + 3][lrow] = pf[q].w;
        }
    }
    __syncthreads();

    int cur = 0;
    for (int iter = 0; iter < NITER; iter++) {
        // global prefetch of next tile into registers
        if (iter < NITER - 1) {
            const int k0n = (iter + 1) * BK;
#pragma unroll
            for (int q = 0; q < 5; q++)
                pf[q] = lok ? *(const float4*)(Lp + k0n + q * 4) : f4z;
        }

        // software-pipelined compute over kk: load kk+1 fragments, then FMA kk
        fa0[0] = *(const float4*)&As[cur][0][r0];
        fa1[0] = *(const float4*)&As[cur][0][r1];
        fb0[0] = *(const float4*)&Bs[cur][0][c0];
        fb1[0] = *(const float4*)&Bs[cur][0][c1];
#pragma unroll
        for (int kk = 0; kk < BK; kk++) {
            const int cb = kk & 1, nb = cb ^ 1;
            if (kk < BK - 1) {
                fa0[nb] = *(const float4*)&As[cur][kk + 1][r0];
                fa1[nb] = *(const float4*)&As[cur][kk + 1][r1];
                fb0[nb] = *(const float4*)&Bs[cur][kk + 1][c0];
                fb1[nb] = *(const float4*)&Bs[cur][kk + 1][c1];
            }
            const float av[8] = {fa0[cb].x, fa0[cb].y, fa0[cb].z, fa0[cb].w,
                                 fa1[cb].x, fa1[cb].y, fa1[cb].z, fa1[cb].w};
            const float bv[8] = {fb0[cb].x, fb0[cb].y, fb0[cb].z, fb0[cb].w,
                                 fb1[cb].x, fb1[cb].y, fb1[cb].z, fb1[cb].w};
#pragma unroll
            for (int i = 0; i < 8; i++)
#pragma unroll
                for (int j = 0; j < 8; j++)
                    acc[i][j] = __fmaf_rn(av[i], bv[j], acc[i][j]);
        }

        if (iter < NITER - 1) {
            const int nxt = cur ^ 1;
            float (*dst)[BM] = isA ? As[nxt] : Bs[nxt];
#pragma unroll
            for (int q = 0; q < 5; q++) {
                dst[q * 4 + 0][lrow] = pf[q].x;  dst[q * 4 + 1][lrow] = pf[q].y;
                dst[q * 4 + 2][lrow] = pf[q].z;  dst[q * 4 + 3][lrow] = pf[q].w;
            }
            __syncthreads();
            cur = nxt;
        }
    }

    // ---- epilogue: total = inp - acc (single rounded subtract), float4 IO ----
#pragma unroll
    for (int i = 0; i < 8; i++) {
        const int m = bm + (i < 4 ? r0 + i : r1 + (i - 4));
        const float* ip = inp + (size_t)m * S_DIM;
        float* op = g_total + (size_t)m * S_DIM;
#pragma unroll
        for (int jg = 0; jg < 2; jg++) {
            const int n0 = bn + (jg == 0 ? c0 : c1);
            if (n0 < S_DIM) {   // n0 % 4 == 0 and S_DIM % 4 == 0 -> all-or-none
                float4 iv = *(const float4*)(ip + n0);
                float4 ov;
                ov.x = __fadd_rn(iv.x, -acc[i][jg * 4 + 0]);
                ov.y = __fadd_rn(iv.y, -acc[i][jg * 4 + 1]);
                ov.z = __fadd_rn(iv.z, -acc[i][jg * 4 + 2]);
                ov.w = __fadd_rn(iv.w, -acc[i][jg * 4 + 3]);
                *(float4*)(op + n0) = ov;
            }
        }
    }
}

// ---------------------------------------------------------------------------
// Kernel 2: sequential scan over T; each thread owns TWO adjacent neurons
// (float2 IO); batch-32 streaming loads for deep MLP at low occupancy.
// Per-lane math identical to validated scalar version (bitwise contract).
// ---------------------------------------------------------------------------
__global__ __launch_bounds__(64) void scan_kernel(
    float* __restrict__ spk_out,
    float* __restrict__ tr_out)
{
    const int p = blockIdx.x * blockDim.x + threadIdx.x;   // pair index
    if (p >= BS / 2) return;

    const float2* tp = (const float2*)g_total + p;
    float2* sp = (float2*)spk_out + p;
    float2* rp = (float2*)tr_out + p;
    const int STRIDE2 = BS / 2;                            // float2 elems per t

    float2 syn = make_float2(0.f, 0.f);
    float2 mem = make_float2(0.f, 0.f);
    float2 tr  = make_float2(0.f, 0.f);

#pragma unroll 1
    for (int t0 = 0; t0 < T_STEPS; t0 += 32) {
        float2 tot[32];
#pragma unroll
        for (int i = 0; i < 32; i++)
            tot[i] = __ldcs(tp + (size_t)(t0 + i) * STRIDE2);

#pragma unroll
        for (int i = 0; i < 32; i++) {
            float2 spk;
            // lane x
            {
                const float reset = (__fadd_rn(mem.x, -THRESH_F) > 0.f) ? 1.f : 0.f;
                syn.x = __fmaf_rn(ALPHA_F, syn.x, tot[i].x);
                mem.x = __fmul_rn(__fmaf_rn(BETA_F, mem.x, syn.x),
                                  __fadd_rn(1.f, -reset));
                spk.x = (__fadd_rn(mem.x, -THRESH_F) > 0.f) ? 1.f : 0.f;
                tr.x  = __fmaf_rn(KAPPA_F, tr.x, spk.x);
            }
            // lane y
            {
                const float reset = (__fadd_rn(mem.y, -THRESH_F) > 0.f) ? 1.f : 0.f;
                syn.y = __fmaf_rn(ALPHA_F, syn.y, tot[i].y);
                mem.y = __fmul_rn(__fmaf_rn(BETA_F, mem.y, syn.y),
                                  __fadd_rn(1.f, -reset));
                spk.y = (__fadd_rn(mem.y, -THRESH_F) > 0.f) ? 1.f : 0.f;
                tr.y  = __fmaf_rn(KAPPA_F, tr.y, spk.y);
            }
            __stcs(sp + (size_t)(t0 + i) * STRIDE2, spk);
            __stcs(rp + (size_t)(t0 + i) * STRIDE2, tr);
        }
    }
}

// ---------------------------------------------------------------------------
extern "C" void kernel_launch(void* const* d_in, const int* in_sizes, int n_in,
                              void* d_out, int out_size)
{
    const float* inp = (const float*)d_in[0];   // input_signal [T, B, S]
    const float* err = (const float*)d_in[1];   // error_signal [T, B, S]
    const float* W   = (const float*)d_in[2];   // W_err [S, S]
    float* out = (float*)d_out;                 // [spks | traces]

    dim3 grid((S_DIM + BN - 1) / BN, M_ROWS / BM);   // (4, 800)
    gemm_total_kernel<<<grid, 256>>>(inp, err, W);

    scan_kernel<<<(BS / 2 + 63) / 64, 64>>>(out, out + (size_t)T_STEPS * BS);
}

// round 12
// speedup vs baseline: 1.0089x; 1.0089x over previous
#include <cuda_runtime.h>

// Problem constants (fixed shapes for SpNCN_Layer_81106162417854)
#define T_STEPS 800
#define BATCH   128
#define S_DIM   500
#define BS      (BATCH * S_DIM)          // 64000
#define M_ROWS  (T_STEPS * BATCH)        // 102400

#define DT     0.25
#define ALPHA_F ((float)(1.0 - DT / 10.0))
#define BETA_F  ((float)(1.0 - DT / 20.0))
#define KAPPA_F ((float)(1.0 - DT / 30.0))
#define THRESH_F 0.4f

// Scratch for total = input - error @ W^T  (205 MB)
__device__ float g_total[(size_t)T_STEPS * BATCH * S_DIM];

// ---------------------------------------------------------------------------
// Kernel 1: total[m,n] = inp[m,n] - sum_k err[m,k] * W[n,k]
// NUMERICS CONTRACT (validated bitwise R4-R11): per output element a serial
// ascending-k single-accumulator scalar FFMA chain; one final __fadd_rn.
// BM=64 x BN=128, BK=16, 128 threads, 8x8 per thread, occ 4 CTAs/SM:
// 4 independent barrier domains per SM (vs 2) to cover sync/LDS bubbles.
// ---------------------------------------------------------------------------
#define BM 64
#define BN 128
#define BK 16
#define KMAIN 496            // 31 * 16
#define NITER 31

__global__ __launch_bounds__(128, 4) void gemm_total_kernel(
    const float* __restrict__ inp,
    const float* __restrict__ err,
    const float* __restrict__ W)
{
    __shared__ float As[2][BK][BM];   // 8 KB
    __shared__ float Bs[2][BK][BN];   // 16 KB

    const int bm = blockIdx.y * BM;
    const int bn = blockIdx.x * BN;
    const int t  = threadIdx.x;       // 0..127

    // ---- load mapping ----
    // A: 64 rows x 4 quads = 256 float4; thread t loads quads {qa, qa+1} of row (t&63)
    const int arow = t & 63;
    const int qa   = (t >> 6) * 2;            // 0 or 2
    // B: 128 rows x 4 quads; thread t loads quads 0..3 of row t
    const int brow = t;
    const float* Ap = err + (size_t)(bm + arow) * S_DIM;
    const bool  bokk = (bn + brow < S_DIM);
    const float* Bp = W + (size_t)(bokk ? bn + brow : 0) * S_DIM;
    const float4 f4z = make_float4(0.f, 0.f, 0.f, 0.f);

    // ---- compute mapping: cx 0..15 (n), ry 0..7 (m) ----
    const int cx = t & 15;
    const int ry = t >> 4;
    const int r0 = ry * 4, r1 = ry * 4 + 32;
    const int c0 = cx * 4, c1 = cx * 4 + 64;

    float acc[8][8];
#pragma unroll
    for (int i = 0; i < 8; i++)
#pragma unroll
        for (int j = 0; j < 8; j++) acc[i][j] = 0.f;

    float4 pa[2], pb[4];
    float4 fa0[2], fa1[2], fb0[2], fb1[2];   // double-buffered fragments

    // ---- prime tile 0 ----
#pragma unroll
    for (int q = 0; q < 2; q++)
        pa[q] = *(const float4*)(Ap + (qa + q) * 4);
#pragma unroll
    for (int q = 0; q < 4; q++)
        pb[q] = bokk ? *(const float4*)(Bp + q * 4) : f4z;
#pragma unroll
    for (int q = 0; q < 2; q++) {
        const int k4 = (qa + q) * 4;
        As[0][k4 + 0][arow] = pa[q].x;  As[0][k4 + 1][arow] = pa[q].y;
        As[0][k4 + 2][arow] = pa[q].z;  As[0][k4 + 3][arow] = pa[q].w;
    }
#pragma unroll
    for (int q = 0; q < 4; q++) {
        Bs[0][q * 4 + 0][brow] = pb[q].x;  Bs[0][q * 4 + 1][brow] = pb[q].y;
        Bs[0][q * 4 + 2][brow] = pb[q].z;  Bs[0][q * 4 + 3][brow] = pb[q].w;
    }
    __syncthreads();

    int cur = 0;
    for (int iter = 0; iter < NITER; iter++) {
        // global prefetch of next tile into registers
        if (iter < NITER - 1) {
            const int k0n = (iter + 1) * BK;
#pragma unroll
            for (int q = 0; q < 2; q++)
                pa[q] = *(const float4*)(Ap + k0n + (qa + q) * 4);
#pragma unroll
            for (int q = 0; q < 4; q++)
                pb[q] = bokk ? *(const float4*)(Bp + k0n + q * 4) : f4z;
        }

        // software-pipelined compute: load kk+1 fragments, then FMA kk
        fa0[0] = *(const float4*)&As[cur][0][r0];
        fa1[0] = *(const float4*)&As[cur][0][r1];
        fb0[0] = *(const float4*)&Bs[cur][0][c0];
        fb1[0] = *(const float4*)&Bs[cur][0][c1];
#pragma unroll
        for (int kk = 0; kk < BK; kk++) {
            const int cb = kk & 1, nb = cb ^ 1;
            if (kk < BK - 1) {
                fa0[nb] = *(const float4*)&As[cur][kk + 1][r0];
                fa1[nb] = *(const float4*)&As[cur][kk + 1][r1];
                fb0[nb] = *(const float4*)&Bs[cur][kk + 1][c0];
                fb1[nb] = *(const float4*)&Bs[cur][kk + 1][c1];
            }
            const float av[8] = {fa0[cb].x, fa0[cb].y, fa0[cb].z, fa0[cb].w,
                                 fa1[cb].x, fa1[cb].y, fa1[cb].z, fa1[cb].w};
            const float bv[8] = {fb0[cb].x, fb0[cb].y, fb0[cb].z, fb0[cb].w,
                                 fb1[cb].x, fb1[cb].y, fb1[cb].z, fb1[cb].w};
#pragma unroll
            for (int i = 0; i < 8; i++)
#pragma unroll
                for (int j = 0; j < 8; j++)
                    acc[i][j] = __fmaf_rn(av[i], bv[j], acc[i][j]);
        }

        if (iter < NITER - 1) {
            const int nxt = cur ^ 1;
#pragma unroll
            for (int q = 0; q < 2; q++) {
                const int k4 = (qa + q) * 4;
                As[nxt][k4 + 0][arow] = pa[q].x;  As[nxt][k4 + 1][arow] = pa[q].y;
                As[nxt][k4 + 2][arow] = pa[q].z;  As[nxt][k4 + 3][arow] = pa[q].w;
            }
#pragma unroll
            for (int q = 0; q < 4; q++) {
                Bs[nxt][q * 4 + 0][brow] = pb[q].x;  Bs[nxt][q * 4 + 1][brow] = pb[q].y;
                Bs[nxt][q * 4 + 2][brow] = pb[q].z;  Bs[nxt][q * 4 + 3][brow] = pb[q].w;
            }
            __syncthreads();
            cur = nxt;
        }
    }

    // ---- K tail: k = 496..499 ----
    __syncthreads();                           // everyone done reading cur
    if (t < 64) {                              // A tail: row t
        float4 v = *(const float4*)(Ap + KMAIN);
        As[0][0][arow] = v.x; As[0][1][arow] = v.y;
        As[0][2][arow] = v.z; As[0][3][arow] = v.w;
    }
    {                                          // B tail: row t (all threads)
        float4 v = bokk ? *(const float4*)(Bp + KMAIN) : f4z;
        Bs[0][0][brow] = v.x; Bs[0][1][brow] = v.y;
        Bs[0][2][brow] = v.z; Bs[0][3][brow] = v.w;
    }
    __syncthreads();
#pragma unroll
    for (int kk = 0; kk < 4; kk++) {
        float4 a0 = *(const float4*)&As[0][kk][r0];
        float4 a1 = *(const float4*)&As[0][kk][r1];
        float4 b0 = *(const float4*)&Bs[0][kk][c0];
        float4 b1 = *(const float4*)&Bs[0][kk][c1];
        const float av[8] = {a0.x, a0.y, a0.z, a0.w, a1.x, a1.y, a1.z, a1.w};
        const float bv[8] = {b0.x, b0.y, b0.z, b0.w, b1.x, b1.y, b1.z, b1.w};
#pragma unroll
        for (int i = 0; i < 8; i++)
#pragma unroll
            for (int j = 0; j < 8; j++)
                acc[i][j] = __fmaf_rn(av[i], bv[j], acc[i][j]);
    }

    // ---- epilogue: total = inp - acc (single rounded subtract), float4 IO ----
#pragma unroll
    for (int i = 0; i < 8; i++) {
        const int m = bm + (i < 4 ? r0 + i : r1 + (i - 4));
        const float* ip = inp + (size_t)m * S_DIM;
        float* op = g_total + (size_t)m * S_DIM;
#pragma unroll
        for (int jg = 0; jg < 2; jg++) {
            const int n0 = bn + (jg == 0 ? c0 : c1);
            if (n0 < S_DIM) {   // n0 % 4 == 0 and S_DIM % 4 == 0 -> all-or-none
                float4 iv = *(const float4*)(ip + n0);
                float4 ov;
                ov.x = __fadd_rn(iv.x, -acc[i][jg * 4 + 0]);
                ov.y = __fadd_rn(iv.y, -acc[i][jg * 4 + 1]);
                ov.z = __fadd_rn(iv.z, -acc[i][jg * 4 + 2]);
                ov.w = __fadd_rn(iv.w, -acc[i][jg * 4 + 3]);
                *(float4*)(op + n0) = ov;
            }
        }
    }
}

// ---------------------------------------------------------------------------
// Kernel 2: sequential scan over T; each thread owns TWO adjacent neurons
// (float2 IO); batch-32 streaming loads for deep MLP at low occupancy.
// Per-lane math identical to validated scalar version (bitwise contract).
// ---------------------------------------------------------------------------
__global__ __launch_bounds__(64) void scan_kernel(
    float* __restrict__ spk_out,
    float* __restrict__ tr_out)
{
    const int p = blockIdx.x * blockDim.x + threadIdx.x;   // pair index
    if (p >= BS / 2) return;

    const float2* tp = (const float2*)g_total + p;
    float2* sp = (float2*)spk_out + p;
    float2* rp = (float2*)tr_out + p;
    const int STRIDE2 = BS / 2;                            // float2 elems per t

    float2 syn = make_float2(0.f, 0.f);
    float2 mem = make_float2(0.f, 0.f);
    float2 tr  = make_float2(0.f, 0.f);

#pragma unroll 1
    for (int t0 = 0; t0 < T_STEPS; t0 += 32) {
        float2 tot[32];
#pragma unroll
        for (int i = 0; i < 32; i++)
            tot[i] = __ldcs(tp + (size_t)(t0 + i) * STRIDE2);

#pragma unroll
        for (int i = 0; i < 32; i++) {
            float2 spk;
            // lane x
            {
                const float reset = (__fadd_rn(mem.x, -THRESH_F) > 0.f) ? 1.f : 0.f;
                syn.x = __fmaf_rn(ALPHA_F, syn.x, tot[i].x);
                mem.x = __fmul_rn(__fmaf_rn(BETA_F, mem.x, syn.x),
                                  __fadd_rn(1.f, -reset));
                spk.x = (__fadd_rn(mem.x, -THRESH_F) > 0.f) ? 1.f : 0.f;
                tr.x  = __fmaf_rn(KAPPA_F, tr.x, spk.x);
            }
            // lane y
            {
                const float reset = (__fadd_rn(mem.y, -THRESH_F) > 0.f) ? 1.f : 0.f;
                syn.y = __fmaf_rn(ALPHA_F, syn.y, tot[i].y);
                mem.y = __fmul_rn(__fmaf_rn(BETA_F, mem.y, syn.y),
                                  __fadd_rn(1.f, -reset));
                spk.y = (__fadd_rn(mem.y, -THRESH_F) > 0.f) ? 1.f : 0.f;
                tr.y  = __fmaf_rn(KAPPA_F, tr.y, spk.y);
            }
            __stcs(sp + (size_t)(t0 + i) * STRIDE2, spk);
            __stcs(rp + (size_t)(t0 + i) * STRIDE2, tr);
        }
    }
}

// ---------------------------------------------------------------------------
extern "C" void kernel_launch(void* const* d_in, const int* in_sizes, int n_in,
                              void* d_out, int out_size)
{
    const float* inp = (const float*)d_in[0];   // input_signal [T, B, S]
    const float* err = (const float*)d_in[1];   // error_signal [T, B, S]
    const float* W   = (const float*)d_in[2];   // W_err [S, S]
    float* out = (float*)d_out;                 // [spks | traces]

    dim3 grid((S_DIM + BN - 1) / BN, M_ROWS / BM);   // (4, 1600)
    gemm_total_kernel<<<grid, 128>>>(inp, err, W);

    scan_kernel<<<(BS / 2 + 63) / 64, 64>>>(out, out + (size_t)T_STEPS * BS);
}